// round 14
// baseline (speedup 1.0000x reference)
#include <cuda_runtime.h>
#include <cuda_bf16.h>
#include <cstdint>
#include <cstddef>

#define B_    64
#define S_    256
#define H_    16
#define D_    256
#define HIDN  4096
#define M_    (B_*S_)
#define SCALE_ 0.0625f

// ---------------- device scratch ----------------
__device__ float g_bv[HIDN];
__device__ __nv_bfloat16 g_xhi[(size_t)M_ * HIDN];
__device__ __nv_bfloat16 g_xlo[(size_t)M_ * HIDN];
__device__ __nv_bfloat16 g_whi[(size_t)4 * HIDN * HIDN];
__device__ __nv_bfloat16 g_wlo[(size_t)4 * HIDN * HIDN];
// projections, bf16 split. Q/K1/K2: [b,h,s,d]; V transposed: [b,h,d,s]
__device__ __nv_bfloat16 g_qhi[(size_t)M_ * HIDN];
__device__ __nv_bfloat16 g_qlo[(size_t)M_ * HIDN];
__device__ __nv_bfloat16 g_k1hi[(size_t)M_ * HIDN];
__device__ __nv_bfloat16 g_k1lo[(size_t)M_ * HIDN];
__device__ __nv_bfloat16 g_k2hi[(size_t)M_ * HIDN];
__device__ __nv_bfloat16 g_k2lo[(size_t)M_ * HIDN];
__device__ __nv_bfloat16 g_vthi[(size_t)M_ * HIDN];
__device__ __nv_bfloat16 g_vtlo[(size_t)M_ * HIDN];

__device__ __forceinline__ uint32_t smem_u32(const void* p) {
    uint32_t a;
    asm("{ .reg .u64 t; cvta.to.shared.u64 t, %1; cvt.u32.u64 %0, t; }" : "=r"(a) : "l"(p));
    return a;
}
__device__ __forceinline__ void cp16(uint32_t d, const void* s) {
    asm volatile("cp.async.cg.shared.global [%0], [%1], 16;" :: "r"(d), "l"(s) : "memory");
}
#define CP_COMMIT() asm volatile("cp.async.commit_group;" ::: "memory")
#define CP_WAIT1()  asm volatile("cp.async.wait_group 1;" ::: "memory")

__device__ __forceinline__ void ldsm4(uint32_t* r, uint32_t addr) {
    asm volatile("ldmatrix.sync.aligned.m8n8.x4.shared.b16 {%0,%1,%2,%3}, [%4];"
        : "=r"(r[0]), "=r"(r[1]), "=r"(r[2]), "=r"(r[3]) : "r"(addr));
}
__device__ __forceinline__ void mma16816(float* c, const uint32_t* a, uint32_t b0, uint32_t b1) {
    asm volatile("mma.sync.aligned.m16n8k16.row.col.f32.bf16.bf16.f32 "
        "{%0,%1,%2,%3}, {%4,%5,%6,%7}, {%8,%9}, {%0,%1,%2,%3};"
        : "+f"(c[0]), "+f"(c[1]), "+f"(c[2]), "+f"(c[3])
        : "r"(a[0]), "r"(a[1]), "r"(a[2]), "r"(a[3]), "r"(b0), "r"(b1));
}
__device__ __forceinline__ uint32_t pack_bf2(float x, float y) {
    __nv_bfloat16 hx = __float2bfloat16_rn(x), hy = __float2bfloat16_rn(y);
    return (uint32_t)__bfloat16_as_ushort(hx) | ((uint32_t)__bfloat16_as_ushort(hy) << 16);
}

__global__ void combine_bv(const float* __restrict__ bv1, const float* __restrict__ bv2) {
    int i = blockIdx.x * blockDim.x + threadIdx.x;
    if (i < HIDN) g_bv[i] = bv1[i] + bv2[i];
}

struct alignas(8) BF4 { __nv_bfloat16 v[4]; };
__global__ void split4(const float* __restrict__ src, __nv_bfloat16* __restrict__ hi,
                       __nv_bfloat16* __restrict__ lo, int n4) {
    int i = blockIdx.x * blockDim.x + threadIdx.x;
    if (i >= n4) return;
    float4 x = ((const float4*)src)[i];
    float a[4] = {x.x, x.y, x.z, x.w};
    BF4 hb, lb;
#pragma unroll
    for (int j = 0; j < 4; j++) {
        __nv_bfloat16 h = __float2bfloat16_rn(a[j]);
        hb.v[j] = h;
        lb.v[j] = __float2bfloat16_rn(a[j] - __bfloat162float(h));
    }
    ((BF4*)hi)[i] = hb;
    ((BF4*)lo)[i] = lb;
}
__global__ void split4sum(const float* __restrict__ s1, const float* __restrict__ s2,
                          __nv_bfloat16* __restrict__ hi, __nv_bfloat16* __restrict__ lo, int n4) {
    int i = blockIdx.x * blockDim.x + threadIdx.x;
    if (i >= n4) return;
    float4 x = ((const float4*)s1)[i];
    float4 y = ((const float4*)s2)[i];
    float a[4] = {x.x + y.x, x.y + y.y, x.z + y.z, x.w + y.w};
    BF4 hb, lb;
#pragma unroll
    for (int j = 0; j < 4; j++) {
        __nv_bfloat16 h = __float2bfloat16_rn(a[j]);
        hb.v[j] = h;
        lb.v[j] = __float2bfloat16_rn(a[j] - __bfloat162float(h));
    }
    ((BF4*)hi)[i] = hb;
    ((BF4*)lo)[i] = lb;
}

// ---------------------------------------------------------------------------
// Projection GEMM: bf16x3 split via mma.sync (R8-proven mainloop).
// Single launch, grid (32, 128, 4). z in {0,1}: Q,K1, full 256 tokens/batch.
// z in {2,3}: K2,V over the compacted 192-token/batch domain; CTAs with
// mt >= 96 exit immediately (mask-dead rows never computed).
// ---------------------------------------------------------------------------
__global__ __launch_bounds__(256, 2) void proj_mma(
    const float* __restrict__ bq, const float* __restrict__ bk1, const float* __restrict__ bk2) {
    extern __shared__ char rawsm[];
    uint32_t sb = smem_u32(rawsm);

    int tid = threadIdx.x;
    int lane = tid & 31, wid = tid >> 5;
    int wm = wid & 1, wn = wid >> 1;
    int nt = blockIdx.x, mt = blockIdx.y;
    int z = blockIdx.z;
    int skip = (z >= 2);
    if (skip && mt >= 96) return;      // mask-dead K2/V rows
    int rbase = mt * 128, cbase = nt * 128;

    const char* srcp[8];
    uint32_t    dst0[8];
#pragma unroll
    for (int i = 0; i < 8; i++) {
        int sidx = tid + i * 256;
        int region = sidx >> 9;
        int idx = sidx & 511;
        int row = idx >> 2, c16 = idx & 3;
        const __nv_bfloat16* base; size_t rg;
        if (region < 2) {
            base = (region == 0) ? g_xhi : g_xlo;
            int t = rbase + row;
            if (skip) { int bx = t / 192; rg = (size_t)(bx * 256 + (t - bx * 192)); }
            else      { rg = (size_t)t; }
        } else {
            base = (region == 2) ? g_whi : g_wlo;
            rg = (size_t)z * HIDN + cbase + row;
        }
        srcp[i] = (const char*)(base + rg * HIDN) + c16 * 16;
        dst0[i] = sb + (uint32_t)region * 8192u + (uint32_t)row * 64u
                + (uint32_t)((c16 ^ (row & 3)) << 4);
    }

    float acc[4][4][4];
#pragma unroll
    for (int a = 0; a < 4; a++)
#pragma unroll
        for (int b = 0; b < 4; b++)
#pragma unroll
            for (int c = 0; c < 4; c++) acc[a][b][c] = 0.f;

    int arow = lane & 15, asel = lane >> 4;
    int brow = ((lane >> 3) & 1) * 8 + (lane & 7);
    int bsel = lane >> 4;

#pragma unroll
    for (int i = 0; i < 8; i++) cp16(dst0[i], srcp[i]);
    CP_COMMIT();

    for (int kt = 0; kt < 128; kt++) {
        if (kt + 1 < 128) {
            uint32_t bo = (uint32_t)((kt + 1) & 1) * 32768u;
            size_t ko = (size_t)(kt + 1) * 64;
#pragma unroll
            for (int i = 0; i < 8; i++) cp16(dst0[i] + bo, srcp[i] + ko);
        }
        CP_COMMIT();
        CP_WAIT1();
        __syncthreads();

        uint32_t sbuf = sb + (uint32_t)(kt & 1) * 32768u;
#pragma unroll
        for (int kk = 0; kk < 2; kk++) {
            uint32_t Bh[2][4], Bl[2][4];
#pragma unroll
            for (int p = 0; p < 2; p++) {
                int r = wn * 32 + p * 16 + brow;
                int c = kk * 2 + bsel;
                uint32_t off = (uint32_t)r * 64u + (uint32_t)((c ^ (r & 3)) << 4);
                ldsm4(Bh[p], sbuf + 16384u + off);
                ldsm4(Bl[p], sbuf + 24576u + off);
            }
#pragma unroll
            for (int tm = 0; tm < 4; tm++) {
                int r = wm * 64 + tm * 16 + arow;
                int c = kk * 2 + asel;
                uint32_t off = (uint32_t)r * 64u + (uint32_t)((c ^ (r & 3)) << 4);
                uint32_t Ah[4], Al[4];
                ldsm4(Ah, sbuf + off);
                ldsm4(Al, sbuf + 8192u + off);
#pragma unroll
                for (int tn = 0; tn < 4; tn++) {
                    int p = tn >> 1, j = tn & 1;
                    mma16816(acc[tm][tn], Ah, Bh[p][j], Bh[p][2 + j]);
                    mma16816(acc[tm][tn], Ah, Bl[p][j], Bl[p][2 + j]);
                    mma16816(acc[tm][tn], Al, Bh[p][j], Bh[p][2 + j]);
                }
            }
        }
        __syncthreads();
    }

    // epilogue: + bias, split -> bf16 hi/lo
    const float* bb = (z == 0) ? bq : (z == 1) ? bk1 : (z == 2) ? bk2 : g_bv;
    __nv_bfloat16* ohi = (z == 0) ? g_qhi : (z == 1) ? g_k1hi : (z == 2) ? g_k2hi : g_vthi;
    __nv_bfloat16* olo = (z == 0) ? g_qlo : (z == 1) ? g_k1lo : (z == 2) ? g_k2lo : g_vtlo;
#pragma unroll
    for (int tn = 0; tn < 4; tn++) {
        int cg = cbase + wn * 32 + tn * 8 + (lane & 3) * 2;
        int h = cg >> 8, d = cg & 255;
        float b0 = bb[cg], b1 = bb[cg + 1];
#pragma unroll
        for (int tm = 0; tm < 4; tm++) {
#pragma unroll
            for (int half = 0; half < 2; half++) {
                int m = rbase + wm * 64 + tm * 16 + (lane >> 2) + half * 8;
                int bb_, s;
                if (skip) { bb_ = m / 192; s = m - bb_ * 192; }
                else      { bb_ = m >> 8;  s = m & 255; }
                float v0 = acc[tm][tn][half * 2 + 0] + b0;
                float v1 = acc[tm][tn][half * 2 + 1] + b1;
                __nv_bfloat16 h0 = __float2bfloat16_rn(v0);
                __nv_bfloat16 h1 = __float2bfloat16_rn(v1);
                __nv_bfloat16 l0 = __float2bfloat16_rn(v0 - __bfloat162float(h0));
                __nv_bfloat16 l1 = __float2bfloat16_rn(v1 - __bfloat162float(h1));
                if (z < 3) {
                    size_t idx = (((size_t)bb_ * H_ + h) * S_ + s) * D_ + d;
                    *(uint32_t*)(ohi + idx) = (uint32_t)__bfloat16_as_ushort(h0)
                                            | ((uint32_t)__bfloat16_as_ushort(h1) << 16);
                    *(uint32_t*)(olo + idx) = (uint32_t)__bfloat16_as_ushort(l0)
                                            | ((uint32_t)__bfloat16_as_ushort(l1) << 16);
                } else {  // V transposed: [b,h,d,s]
                    size_t base = ((size_t)bb_ * H_ + h) * (S_ * D_) + s;
                    ohi[base + (size_t)d * S_]       = h0;
                    ohi[base + (size_t)(d + 1) * S_] = h1;
                    olo[base + (size_t)d * S_]       = l0;
                    olo[base + (size_t)(d + 1) * S_] = l1;
                }
            }
        }
    }
}

// ---------------------------------------------------------------------------
// Attention via mma.sync, bf16x3. Phase 2 now uses ALL 8 warps (48 cols each).
// ---------------------------------------------------------------------------
#define SB_OFF   0u
#define SA_OFF   65536u
#define S1HI_OFF 81920u
#define S1LO_OFF 115712u
#define SCR_OFF  81920u
#define PHI_OFF  149504u
#define PLO_OFF  175104u
#define ATTN_SMEM 200704

__global__ __launch_bounds__(256, 1) void attn_mma(float* __restrict__ out) {
    extern __shared__ char sm[];
    uint32_t sb = smem_u32(sm);
    int tid = threadIdx.x, lane = tid & 31, wid = tid >> 5;
    int wm = wid & 1, wn = wid >> 1;
    int qb = blockIdx.x, h = blockIdx.y, b = blockIdx.z;
    int bh = b * H_ + h;
    size_t bho = (size_t)bh * (S_ * D_);

    const __nv_bfloat16* Qh  = g_qhi  + bho; const __nv_bfloat16* Ql  = g_qlo  + bho;
    const __nv_bfloat16* K1h = g_k1hi + bho; const __nv_bfloat16* K1l = g_k1lo + bho;
    const __nv_bfloat16* K2h = g_k2hi + bho; const __nv_bfloat16* K2l = g_k2lo + bho;
    const __nv_bfloat16* Vh  = g_vthi + bho; const __nv_bfloat16* Vl  = g_vtlo + bho;

    int arow = lane & 15, asel = lane >> 4;
    int brow = ((lane >> 3) & 1) * 8 + (lane & 7);
    int bsel = lane >> 4;

    float acc[2][8][4];

#define STAGE_B256(HP, LP, st, kt) do { \
    _Pragma("unroll") \
    for (int i = 0; i < 8; i++) { \
        int sidx = tid + i * 256; \
        int reg = sidx >> 10, idx = sidx & 1023; \
        int row = idx >> 2, c16 = idx & 3; \
        const __nv_bfloat16* s_ = (reg ? (LP) : (HP)) + (size_t)row * 256 + (kt) * 32 + c16 * 8; \
        uint32_t d_ = sb + SB_OFF + (uint32_t)(st) * 32768u + (uint32_t)reg * 16384u \
                    + (uint32_t)row * 64u + (uint32_t)((c16 ^ (row & 3)) << 4); \
        cp16(d_, s_); \
    } } while (0)

#define STAGE_B192(HP, LP, st, kt) do { \
    _Pragma("unroll") \
    for (int i = 0; i < 6; i++) { \
        int sidx = tid + i * 256; \
        int reg = sidx >= 768 ? 1 : 0; \
        int idx = sidx - reg * 768; \
        int row = idx >> 2, c16 = idx & 3; \
        const __nv_bfloat16* s_ = (reg ? (LP) : (HP)) + (size_t)row * 256 + (kt) * 32 + c16 * 8; \
        uint32_t d_ = sb + SB_OFF + (uint32_t)(st) * 32768u + (uint32_t)reg * 16384u \
                    + (uint32_t)row * 64u + (uint32_t)((c16 ^ (row & 3)) << 4); \
        cp16(d_, s_); \
    } } while (0)

#define STAGE_A64(HP, LP, st, kt) do { \
    _Pragma("unroll") \
    for (int i = 0; i < 2; i++) { \
        int sidx = tid + i * 256; \
        int reg = sidx >> 8, idx = sidx & 255; \
        int row = idx >> 2, c16 = idx & 3; \
        const __nv_bfloat16* s_ = (reg ? (LP) : (HP)) + (size_t)(qb * 64 + row) * 256 + (kt) * 32 + c16 * 8; \
        uint32_t d_ = sb + SA_OFF + (uint32_t)(st) * 8192u + (uint32_t)reg * 4096u \
                    + (uint32_t)row * 64u + (uint32_t)((c16 ^ (row & 3)) << 4); \
        cp16(d_, s_); \
    } } while (0)

#define LOAD_B(Bh, Bl, bufB, kk) do { \
    _Pragma("unroll") \
    for (int ng = 0; ng < 4; ng++) { \
        int r_ = wn * 64 + ng * 16 + brow; \
        int c_ = (kk) * 2 + bsel; \
        uint32_t off_ = (uint32_t)r_ * 64u + (uint32_t)((c_ ^ (r_ & 3)) << 4); \
        ldsm4(Bh[ng], (bufB) + off_); \
        ldsm4(Bl[ng], (bufB) + 16384u + off_); \
    } } while (0)

// phase-2 variant: 48 rows (3 ng groups) per warp
#define LOAD_B48(Bh, Bl, bufB, kk) do { \
    _Pragma("unroll") \
    for (int ng = 0; ng < 3; ng++) { \
        int r_ = wn * 48 + ng * 16 + brow; \
        int c_ = (kk) * 2 + bsel; \
        uint32_t off_ = (uint32_t)r_ * 64u + (uint32_t)((c_ ^ (r_ & 3)) << 4); \
        ldsm4(Bh[ng], (bufB) + off_); \
        ldsm4(Bl[ng], (bufB) + 16384u + off_); \
    } } while (0)

#define DO_MMAS(Bh, Bl, Ah, Al) do { \
    _Pragma("unroll") \
    for (int tm = 0; tm < 2; tm++) \
    _Pragma("unroll") \
    for (int ng = 0; ng < 4; ng++) \
    _Pragma("unroll") \
    for (int j = 0; j < 2; j++) { \
        int tn = ng * 2 + j; \
        mma16816(acc[tm][tn], Ah[tm], Bh[ng][j], Bh[ng][2 + j]); \
        mma16816(acc[tm][tn], Ah[tm], Bl[ng][j], Bl[ng][2 + j]); \
        mma16816(acc[tm][tn], Al[tm], Bh[ng][j], Bh[ng][2 + j]); \
    } } while (0)

#define DO_MMAS6(Bh, Bl, Ah, Al) do { \
    _Pragma("unroll") \
    for (int tm = 0; tm < 2; tm++) \
    _Pragma("unroll") \
    for (int ng = 0; ng < 3; ng++) \
    _Pragma("unroll") \
    for (int j = 0; j < 2; j++) { \
        int tn = ng * 2 + j; \
        mma16816(acc[tm][tn], Ah[tm], Bh[ng][j], Bh[ng][2 + j]); \
        mma16816(acc[tm][tn], Ah[tm], Bl[ng][j], Bl[ng][2 + j]); \
        mma16816(acc[tm][tn], Al[tm], Bh[ng][j], Bh[ng][2 + j]); \
    } } while (0)

    // ===== phase 1: s1 = Q @ K1^T =====
#pragma unroll
    for (int a = 0; a < 2; a++)
#pragma unroll
        for (int b2 = 0; b2 < 8; b2++)
#pragma unroll
            for (int c = 0; c < 4; c++) acc[a][b2][c] = 0.f;

    STAGE_B256(K1h, K1l, 0, 0);
    STAGE_A64(Qh, Ql, 0, 0);
    CP_COMMIT();
    for (int kt = 0; kt < 8; kt++) {
        if (kt + 1 < 8) {
            STAGE_B256(K1h, K1l, (kt + 1) & 1, kt + 1);
            STAGE_A64(Qh, Ql, (kt + 1) & 1, kt + 1);
        }
        CP_COMMIT(); CP_WAIT1(); __syncthreads();
        uint32_t bufB = sb + SB_OFF + (uint32_t)(kt & 1) * 32768u;
        uint32_t bufA = sb + SA_OFF + (uint32_t)(kt & 1) * 8192u;
#pragma unroll
        for (int kk = 0; kk < 2; kk++) {
            uint32_t Bh[4][4], Bl[4][4], Ah[2][4], Al[2][4];
            LOAD_B(Bh, Bl, bufB, kk);
#pragma unroll
            for (int tm = 0; tm < 2; tm++) {
                int r = wm * 32 + tm * 16 + arow;
                int c = kk * 2 + asel;
                uint32_t off = (uint32_t)r * 64u + (uint32_t)((c ^ (r & 3)) << 4);
                ldsm4(Ah[tm], bufA + off);
                ldsm4(Al[tm], bufA + 4096u + off);
            }
            DO_MMAS(Bh, Bl, Ah, Al);
        }
        __syncthreads();
    }
#pragma unroll
    for (int tm = 0; tm < 2; tm++)
#pragma unroll
        for (int tn = 0; tn < 8; tn++)
#pragma unroll
            for (int half = 0; half < 2; half++) {
                int m = wm * 32 + tm * 16 + (lane >> 2) + half * 8;
                int n = wn * 64 + tn * 8 + (lane & 3) * 2;
                float v0 = acc[tm][tn][half * 2 + 0];
                float v1 = acc[tm][tn][half * 2 + 1];
                __nv_bfloat16 h0 = __float2bfloat16_rn(v0), h1 = __float2bfloat16_rn(v1);
                float l0 = v0 - __bfloat162float(h0), l1 = v1 - __bfloat162float(h1);
                *(uint32_t*)(sm + S1HI_OFF + m * 528 + n * 2) =
                    (uint32_t)__bfloat16_as_ushort(h0) | ((uint32_t)__bfloat16_as_ushort(h1) << 16);
                *(uint32_t*)(sm + S1LO_OFF + m * 528 + n * 2) = pack_bf2(l0, l1);
            }
    __syncthreads();

    // ===== phase 2: scores(:, :192) = s1 @ K2^T * SCALE — all 8 warps, 48 cols each =====
#pragma unroll
    for (int a = 0; a < 2; a++)
#pragma unroll
        for (int b2 = 0; b2 < 8; b2++)
#pragma unroll
            for (int c = 0; c < 4; c++) acc[a][b2][c] = 0.f;

    STAGE_B192(K2h, K2l, 0, 0);
    CP_COMMIT();
    for (int kt = 0; kt < 8; kt++) {
        if (kt + 1 < 8) STAGE_B192(K2h, K2l, (kt + 1) & 1, kt + 1);
        CP_COMMIT(); CP_WAIT1(); __syncthreads();
        {
            uint32_t bufB = sb + SB_OFF + (uint32_t)(kt & 1) * 32768u;
#pragma unroll
            for (int kk = 0; kk < 2; kk++) {
                uint32_t Bh[3][4], Bl[3][4], Ah[2][4], Al[2][4];
                LOAD_B48(Bh, Bl, bufB, kk);
#pragma unroll
                for (int tm = 0; tm < 2; tm++) {
                    int r = wm * 32 + tm * 16 + arow;
                    uint32_t co = (uint32_t)(kt * 32 + kk * 16 + asel * 8) * 2u;
                    ldsm4(Ah[tm], sb + S1HI_OFF + (uint32_t)r * 528u + co);
                    ldsm4(Al[tm], sb + S1LO_OFF + (uint32_t)r * 528u + co);
                }
                DO_MMAS6(Bh, Bl, Ah, Al);
            }
        }
        __syncthreads();
    }
    {
#pragma unroll
        for (int tm = 0; tm < 2; tm++)
#pragma unroll
            for (int tn = 0; tn < 6; tn++)
#pragma unroll
                for (int half = 0; half < 2; half++) {
                    int m = wm * 32 + tm * 16 + (lane >> 2) + half * 8;
                    int n = wn * 48 + tn * 8 + (lane & 3) * 2;
                    float2 v = make_float2(acc[tm][tn][half * 2 + 0] * SCALE_,
                                           acc[tm][tn][half * 2 + 1] * SCALE_);
                    *(float2*)(sm + SCR_OFF + m * 768 + n * 4) = v;
                }
    }
    __syncthreads();

    // ===== softmax over 192 cols, split P -> bf16 hi/lo =====
    {
#pragma unroll
        for (int i = 0; i < 8; i++) {
            int r = wid * 8 + i;
            const float* row = (const float*)(sm + SCR_OFF + r * 768);
            float mx = -1e30f;
#pragma unroll
            for (int c = 0; c < 6; c++) mx = fmaxf(mx, row[lane + c * 32]);
#pragma unroll
            for (int o = 16; o; o >>= 1) mx = fmaxf(mx, __shfl_xor_sync(0xffffffffu, mx, o));
            float e[6], ssum = 0.f;
#pragma unroll
            for (int c = 0; c < 6; c++) { e[c] = expf(row[lane + c * 32] - mx); ssum += e[c]; }
#pragma unroll
            for (int o = 16; o; o >>= 1) ssum += __shfl_xor_sync(0xffffffffu, ssum, o);
            float inv = 1.f / ssum;
#pragma unroll
            for (int c = 0; c < 6; c++) {
                float p = e[c] * inv;
                __nv_bfloat16 ph = __float2bfloat16_rn(p);
                __nv_bfloat16 pl = __float2bfloat16_rn(p - __bfloat162float(ph));
                int col = lane + c * 32;
                *(__nv_bfloat16*)(sm + PHI_OFF + r * 400 + col * 2) = ph;
                *(__nv_bfloat16*)(sm + PLO_OFF + r * 400 + col * 2) = pl;
            }
        }
    }
    __syncthreads();

    // ===== phase 3: ctx = P[:, :192] @ V^T =====
#pragma unroll
    for (int a = 0; a < 2; a++)
#pragma unroll
        for (int b2 = 0; b2 < 8; b2++)
#pragma unroll
            for (int c = 0; c < 4; c++) acc[a][b2][c] = 0.f;

    STAGE_B256(Vh, Vl, 0, 0);
    CP_COMMIT();
    for (int kt = 0; kt < 6; kt++) {
        if (kt + 1 < 6) STAGE_B256(Vh, Vl, (kt + 1) & 1, kt + 1);
        CP_COMMIT(); CP_WAIT1(); __syncthreads();
        uint32_t bufB = sb + SB_OFF + (uint32_t)(kt & 1) * 32768u;
#pragma unroll
        for (int kk = 0; kk < 2; kk++) {
            uint32_t Bh[4][4], Bl[4][4], Ah[2][4], Al[2][4];
            LOAD_B(Bh, Bl, bufB, kk);
#pragma unroll
            for (int tm = 0; tm < 2; tm++) {
                int r = wm * 32 + tm * 16 + arow;
                uint32_t co = (uint32_t)(kt * 32 + kk * 16 + asel * 8) * 2u;
                ldsm4(Ah[tm], sb + PHI_OFF + (uint32_t)r * 400u + co);
                ldsm4(Al[tm], sb + PLO_OFF + (uint32_t)r * 400u + co);
            }
            DO_MMAS(Bh, Bl, Ah, Al);
        }
        __syncthreads();
    }
#pragma unroll
    for (int tm = 0; tm < 2; tm++)
#pragma unroll
        for (int tn = 0; tn < 8; tn++)
#pragma unroll
            for (int half = 0; half < 2; half++) {
                int m = wm * 32 + tm * 16 + (lane >> 2) + half * 8;
                int n = wn * 64 + tn * 8 + (lane & 3) * 2;
                int s = qb * 64 + m;
                float2 v = make_float2(acc[tm][tn][half * 2 + 0], acc[tm][tn][half * 2 + 1]);
                *(float2*)(out + ((size_t)(b * S_ + s)) * HIDN + h * D_ + n) = v;
            }
}

extern "C" void kernel_launch(void* const* d_in, const int* in_sizes, int n_in,
                              void* d_out, int out_size) {
    const float* X   = (const float*)d_in[0];
    const float* wq  = (const float*)d_in[1];
    const float* bq  = (const float*)d_in[2];
    const float* wk1 = (const float*)d_in[3];
    const float* bk1 = (const float*)d_in[4];
    const float* wk2 = (const float*)d_in[5];
    const float* bk2 = (const float*)d_in[6];
    const float* wv1 = (const float*)d_in[7];
    const float* bv1 = (const float*)d_in[8];
    const float* wv2 = (const float*)d_in[9];
    const float* bv2 = (const float*)d_in[10];
    float* out = (float*)d_out;

    static __nv_bfloat16 *whi = nullptr, *wlo = nullptr, *xhi = nullptr, *xlo = nullptr;
    if (!whi) {
        cudaGetSymbolAddress((void**)&whi, g_whi);
        cudaGetSymbolAddress((void**)&wlo, g_wlo);
        cudaGetSymbolAddress((void**)&xhi, g_xhi);
        cudaGetSymbolAddress((void**)&xlo, g_xlo);
    }

    combine_bv<<<HIDN / 256, 256>>>(bv1, bv2);

    const int NW4 = (HIDN * HIDN) / 4;
    const int NX4 = (M_ * HIDN) / 4;
    split4<<<NX4 / 256, 256>>>(X,   xhi, xlo, NX4);
    split4<<<NW4 / 256, 256>>>(wq,  whi + (size_t)0 * HIDN * HIDN, wlo + (size_t)0 * HIDN * HIDN, NW4);
    split4<<<NW4 / 256, 256>>>(wk1, whi + (size_t)1 * HIDN * HIDN, wlo + (size_t)1 * HIDN * HIDN, NW4);
    split4<<<NW4 / 256, 256>>>(wk2, whi + (size_t)2 * HIDN * HIDN, wlo + (size_t)2 * HIDN * HIDN, NW4);
    split4sum<<<NW4 / 256, 256>>>(wv1, wv2,
                                  whi + (size_t)3 * HIDN * HIDN, wlo + (size_t)3 * HIDN * HIDN, NW4);

    const int proj_smem = 65536;
    cudaFuncSetAttribute(proj_mma, cudaFuncAttributeMaxDynamicSharedMemorySize, proj_smem);
    dim3 gproj(HIDN / 128, M_ / 128, 4);    // one launch; z>=2 CTAs with mt>=96 exit
    proj_mma<<<gproj, 256, proj_smem>>>(bq, bk1, bk2);

    cudaFuncSetAttribute(attn_mma, cudaFuncAttributeMaxDynamicSharedMemorySize, ATTN_SMEM);
    dim3 gattn(4, H_, B_);
    attn_mma<<<gattn, 256, ATTN_SMEM>>>(out);
}

// round 15
// speedup vs baseline: 1.0055x; 1.0055x over previous
#include <cuda_runtime.h>
#include <cuda_bf16.h>
#include <cstdint>
#include <cstddef>

#define B_    64
#define S_    256
#define H_    16
#define D_    256
#define HIDN  4096
#define M_    (B_*S_)
#define SCALE_ 0.0625f

// ---------------- device scratch ----------------
__device__ float g_bv[HIDN];
__device__ __nv_bfloat16 g_xhi[(size_t)M_ * HIDN];
__device__ __nv_bfloat16 g_xlo[(size_t)M_ * HIDN];
__device__ __nv_bfloat16 g_whi[(size_t)4 * HIDN * HIDN];
__device__ __nv_bfloat16 g_wlo[(size_t)4 * HIDN * HIDN];
// projections, bf16 split. Q/K1/K2: [b,h,s,d]; V transposed: [b,h,d,s]
__device__ __nv_bfloat16 g_qhi[(size_t)M_ * HIDN];
__device__ __nv_bfloat16 g_qlo[(size_t)M_ * HIDN];
__device__ __nv_bfloat16 g_k1hi[(size_t)M_ * HIDN];
__device__ __nv_bfloat16 g_k1lo[(size_t)M_ * HIDN];
__device__ __nv_bfloat16 g_k2hi[(size_t)M_ * HIDN];
__device__ __nv_bfloat16 g_k2lo[(size_t)M_ * HIDN];
__device__ __nv_bfloat16 g_vthi[(size_t)M_ * HIDN];
__device__ __nv_bfloat16 g_vtlo[(size_t)M_ * HIDN];

__device__ __forceinline__ uint32_t smem_u32(const void* p) {
    uint32_t a;
    asm("{ .reg .u64 t; cvta.to.shared.u64 t, %1; cvt.u32.u64 %0, t; }" : "=r"(a) : "l"(p));
    return a;
}
__device__ __forceinline__ void cp16(uint32_t d, const void* s) {
    asm volatile("cp.async.cg.shared.global [%0], [%1], 16;" :: "r"(d), "l"(s) : "memory");
}
#define CP_COMMIT() asm volatile("cp.async.commit_group;" ::: "memory")
#define CP_WAIT1()  asm volatile("cp.async.wait_group 1;" ::: "memory")

__device__ __forceinline__ void ldsm4(uint32_t* r, uint32_t addr) {
    asm volatile("ldmatrix.sync.aligned.m8n8.x4.shared.b16 {%0,%1,%2,%3}, [%4];"
        : "=r"(r[0]), "=r"(r[1]), "=r"(r[2]), "=r"(r[3]) : "r"(addr));
}
__device__ __forceinline__ void mma16816(float* c, const uint32_t* a, uint32_t b0, uint32_t b1) {
    asm volatile("mma.sync.aligned.m16n8k16.row.col.f32.bf16.bf16.f32 "
        "{%0,%1,%2,%3}, {%4,%5,%6,%7}, {%8,%9}, {%0,%1,%2,%3};"
        : "+f"(c[0]), "+f"(c[1]), "+f"(c[2]), "+f"(c[3])
        : "r"(a[0]), "r"(a[1]), "r"(a[2]), "r"(a[3]), "r"(b0), "r"(b1));
}
__device__ __forceinline__ uint32_t pack_bf2(float x, float y) {
    __nv_bfloat16 hx = __float2bfloat16_rn(x), hy = __float2bfloat16_rn(y);
    return (uint32_t)__bfloat16_as_ushort(hx) | ((uint32_t)__bfloat16_as_ushort(hy) << 16);
}

__global__ void combine_bv(const float* __restrict__ bv1, const float* __restrict__ bv2) {
    int i = blockIdx.x * blockDim.x + threadIdx.x;
    if (i < HIDN) g_bv[i] = bv1[i] + bv2[i];
}

struct alignas(8) BF4 { __nv_bfloat16 v[4]; };
__global__ void split4(const float* __restrict__ src, __nv_bfloat16* __restrict__ hi,
                       __nv_bfloat16* __restrict__ lo, int n4) {
    int i = blockIdx.x * blockDim.x + threadIdx.x;
    if (i >= n4) return;
    float4 x = ((const float4*)src)[i];
    float a[4] = {x.x, x.y, x.z, x.w};
    BF4 hb, lb;
#pragma unroll
    for (int j = 0; j < 4; j++) {
        __nv_bfloat16 h = __float2bfloat16_rn(a[j]);
        hb.v[j] = h;
        lb.v[j] = __float2bfloat16_rn(a[j] - __bfloat162float(h));
    }
    ((BF4*)hi)[i] = hb;
    ((BF4*)lo)[i] = lb;
}
__global__ void split4sum(const float* __restrict__ s1, const float* __restrict__ s2,
                          __nv_bfloat16* __restrict__ hi, __nv_bfloat16* __restrict__ lo, int n4) {
    int i = blockIdx.x * blockDim.x + threadIdx.x;
    if (i >= n4) return;
    float4 x = ((const float4*)s1)[i];
    float4 y = ((const float4*)s2)[i];
    float a[4] = {x.x + y.x, x.y + y.y, x.z + y.z, x.w + y.w};
    BF4 hb, lb;
#pragma unroll
    for (int j = 0; j < 4; j++) {
        __nv_bfloat16 h = __float2bfloat16_rn(a[j]);
        hb.v[j] = h;
        lb.v[j] = __float2bfloat16_rn(a[j] - __bfloat162float(h));
    }
    ((BF4*)hi)[i] = hb;
    ((BF4*)lo)[i] = lb;
}

// ---------------------------------------------------------------------------
// Projection GEMM (unchanged from R13/R14 passing version).
// ---------------------------------------------------------------------------
__global__ __launch_bounds__(256, 2) void proj_mma(
    const float* __restrict__ bq, const float* __restrict__ bk1, const float* __restrict__ bk2) {
    extern __shared__ char rawsm[];
    uint32_t sb = smem_u32(rawsm);

    int tid = threadIdx.x;
    int lane = tid & 31, wid = tid >> 5;
    int wm = wid & 1, wn = wid >> 1;
    int nt = blockIdx.x, mt = blockIdx.y;
    int z = blockIdx.z;
    int skip = (z >= 2);
    if (skip && mt >= 96) return;
    int rbase = mt * 128, cbase = nt * 128;

    const char* srcp[8];
    uint32_t    dst0[8];
#pragma unroll
    for (int i = 0; i < 8; i++) {
        int sidx = tid + i * 256;
        int region = sidx >> 9;
        int idx = sidx & 511;
        int row = idx >> 2, c16 = idx & 3;
        const __nv_bfloat16* base; size_t rg;
        if (region < 2) {
            base = (region == 0) ? g_xhi : g_xlo;
            int t = rbase + row;
            if (skip) { int bx = t / 192; rg = (size_t)(bx * 256 + (t - bx * 192)); }
            else      { rg = (size_t)t; }
        } else {
            base = (region == 2) ? g_whi : g_wlo;
            rg = (size_t)z * HIDN + cbase + row;
        }
        srcp[i] = (const char*)(base + rg * HIDN) + c16 * 16;
        dst0[i] = sb + (uint32_t)region * 8192u + (uint32_t)row * 64u
                + (uint32_t)((c16 ^ (row & 3)) << 4);
    }

    float acc[4][4][4];
#pragma unroll
    for (int a = 0; a < 4; a++)
#pragma unroll
        for (int b = 0; b < 4; b++)
#pragma unroll
            for (int c = 0; c < 4; c++) acc[a][b][c] = 0.f;

    int arow = lane & 15, asel = lane >> 4;
    int brow = ((lane >> 3) & 1) * 8 + (lane & 7);
    int bsel = lane >> 4;

#pragma unroll
    for (int i = 0; i < 8; i++) cp16(dst0[i], srcp[i]);
    CP_COMMIT();

    for (int kt = 0; kt < 128; kt++) {
        if (kt + 1 < 128) {
            uint32_t bo = (uint32_t)((kt + 1) & 1) * 32768u;
            size_t ko = (size_t)(kt + 1) * 64;
#pragma unroll
            for (int i = 0; i < 8; i++) cp16(dst0[i] + bo, srcp[i] + ko);
        }
        CP_COMMIT();
        CP_WAIT1();
        __syncthreads();

        uint32_t sbuf = sb + (uint32_t)(kt & 1) * 32768u;
#pragma unroll
        for (int kk = 0; kk < 2; kk++) {
            uint32_t Bh[2][4], Bl[2][4];
#pragma unroll
            for (int p = 0; p < 2; p++) {
                int r = wn * 32 + p * 16 + brow;
                int c = kk * 2 + bsel;
                uint32_t off = (uint32_t)r * 64u + (uint32_t)((c ^ (r & 3)) << 4);
                ldsm4(Bh[p], sbuf + 16384u + off);
                ldsm4(Bl[p], sbuf + 24576u + off);
            }
#pragma unroll
            for (int tm = 0; tm < 4; tm++) {
                int r = wm * 64 + tm * 16 + arow;
                int c = kk * 2 + asel;
                uint32_t off = (uint32_t)r * 64u + (uint32_t)((c ^ (r & 3)) << 4);
                uint32_t Ah[4], Al[4];
                ldsm4(Ah, sbuf + off);
                ldsm4(Al, sbuf + 8192u + off);
#pragma unroll
                for (int tn = 0; tn < 4; tn++) {
                    int p = tn >> 1, j = tn & 1;
                    mma16816(acc[tm][tn], Ah, Bh[p][j], Bh[p][2 + j]);
                    mma16816(acc[tm][tn], Ah, Bl[p][j], Bl[p][2 + j]);
                    mma16816(acc[tm][tn], Al, Bh[p][j], Bh[p][2 + j]);
                }
            }
        }
        __syncthreads();
    }

    const float* bb = (z == 0) ? bq : (z == 1) ? bk1 : (z == 2) ? bk2 : g_bv;
    __nv_bfloat16* ohi = (z == 0) ? g_qhi : (z == 1) ? g_k1hi : (z == 2) ? g_k2hi : g_vthi;
    __nv_bfloat16* olo = (z == 0) ? g_qlo : (z == 1) ? g_k1lo : (z == 2) ? g_k2lo : g_vtlo;
#pragma unroll
    for (int tn = 0; tn < 4; tn++) {
        int cg = cbase + wn * 32 + tn * 8 + (lane & 3) * 2;
        int h = cg >> 8, d = cg & 255;
        float b0 = bb[cg], b1 = bb[cg + 1];
#pragma unroll
        for (int tm = 0; tm < 4; tm++) {
#pragma unroll
            for (int half = 0; half < 2; half++) {
                int m = rbase + wm * 64 + tm * 16 + (lane >> 2) + half * 8;
                int bb_, s;
                if (skip) { bb_ = m / 192; s = m - bb_ * 192; }
                else      { bb_ = m >> 8;  s = m & 255; }
                float v0 = acc[tm][tn][half * 2 + 0] + b0;
                float v1 = acc[tm][tn][half * 2 + 1] + b1;
                __nv_bfloat16 h0 = __float2bfloat16_rn(v0);
                __nv_bfloat16 h1 = __float2bfloat16_rn(v1);
                __nv_bfloat16 l0 = __float2bfloat16_rn(v0 - __bfloat162float(h0));
                __nv_bfloat16 l1 = __float2bfloat16_rn(v1 - __bfloat162float(h1));
                if (z < 3) {
                    size_t idx = (((size_t)bb_ * H_ + h) * S_ + s) * D_ + d;
                    *(uint32_t*)(ohi + idx) = (uint32_t)__bfloat16_as_ushort(h0)
                                            | ((uint32_t)__bfloat16_as_ushort(h1) << 16);
                    *(uint32_t*)(olo + idx) = (uint32_t)__bfloat16_as_ushort(l0)
                                            | ((uint32_t)__bfloat16_as_ushort(l1) << 16);
                } else {
                    size_t base = ((size_t)bb_ * H_ + h) * (S_ * D_) + s;
                    ohi[base + (size_t)d * S_]       = h0;
                    ohi[base + (size_t)(d + 1) * S_] = h1;
                    olo[base + (size_t)d * S_]       = l0;
                    olo[base + (size_t)(d + 1) * S_] = l1;
                }
            }
        }
    }
}

// ---------------------------------------------------------------------------
// Attention: same math, smem diet to 108.5 KB -> occupancy 2.
// 16-col staging chunks (32B rows), P embedded in 784B-stride SCR rows.
// ---------------------------------------------------------------------------
#define SB_OFF   0u        // 2 stages x 16 KB (hi 8K + lo 8K per stage)
#define SA_OFF   32768u    // 2 stages x 4 KB
#define S1HI_OFF 40960u    // 64 x 528 B
#define S1LO_OFF 74752u    // 64 x 528 B (end 108544)
#define SCR_OFF  40960u    // alias over S1: 64 rows x 784 B (ends 91136)
#define ATTN_SMEM 108544

__global__ __launch_bounds__(256, 2) void attn_mma(float* __restrict__ out) {
    extern __shared__ char sm[];
    uint32_t sb = smem_u32(sm);
    int tid = threadIdx.x, lane = tid & 31, wid = tid >> 5;
    int wm = wid & 1, wn = wid >> 1;
    int qb = blockIdx.x, h = blockIdx.y, b = blockIdx.z;
    int bh = b * H_ + h;
    size_t bho = (size_t)bh * (S_ * D_);

    const __nv_bfloat16* Qh  = g_qhi  + bho; const __nv_bfloat16* Ql  = g_qlo  + bho;
    const __nv_bfloat16* K1h = g_k1hi + bho; const __nv_bfloat16* K1l = g_k1lo + bho;
    const __nv_bfloat16* K2h = g_k2hi + bho; const __nv_bfloat16* K2l = g_k2lo + bho;
    const __nv_bfloat16* Vh  = g_vthi + bho; const __nv_bfloat16* Vl  = g_vtlo + bho;

    int arow = lane & 15, asel = lane >> 4;
    int brow = ((lane >> 3) & 1) * 8 + (lane & 7);
    int bsel = lane >> 4;

    float acc[2][8][4];

// stage 256 rows x 16 cols (32B/row) hi+lo: 1024 cp16, 4/thread
#define STAGE_B256(HP, LP, st, kt) do { \
    _Pragma("unroll") \
    for (int i = 0; i < 4; i++) { \
        int sidx = tid + i * 256; \
        int reg = sidx >> 9, idx = sidx & 511; \
        int row = idx >> 1, c16 = idx & 1; \
        const __nv_bfloat16* s_ = (reg ? (LP) : (HP)) + (size_t)row * 256 + (kt) * 16 + c16 * 8; \
        uint32_t d_ = sb + SB_OFF + (uint32_t)(st) * 16384u + (uint32_t)reg * 8192u \
                    + (uint32_t)row * 32u + (uint32_t)((c16 ^ ((row >> 2) & 1)) << 4); \
        cp16(d_, s_); \
    } } while (0)

// stage 192 rows x 16 cols hi+lo: 768 cp16, 3/thread
#define STAGE_B192(HP, LP, st, kt) do { \
    _Pragma("unroll") \
    for (int i = 0; i < 3; i++) { \
        int sidx = tid + i * 256; \
        int reg = sidx >= 384 ? 1 : 0; \
        int idx = sidx - reg * 384; \
        int row = idx >> 1, c16 = idx & 1; \
        const __nv_bfloat16* s_ = (reg ? (LP) : (HP)) + (size_t)row * 256 + (kt) * 16 + c16 * 8; \
        uint32_t d_ = sb + SB_OFF + (uint32_t)(st) * 16384u + (uint32_t)reg * 8192u \
                    + (uint32_t)row * 32u + (uint32_t)((c16 ^ ((row >> 2) & 1)) << 4); \
        cp16(d_, s_); \
    } } while (0)

// stage 64 rows x 16 cols hi+lo: 256 cp16, 1/thread
#define STAGE_A64(HP, LP, st, kt) do { \
    { \
        int sidx = tid; \
        int reg = sidx >> 7, idx = sidx & 127; \
        int row = idx >> 1, c16 = idx & 1; \
        const __nv_bfloat16* s_ = (reg ? (LP) : (HP)) + (size_t)(qb * 64 + row) * 256 + (kt) * 16 + c16 * 8; \
        uint32_t d_ = sb + SA_OFF + (uint32_t)(st) * 4096u + (uint32_t)reg * 2048u \
                    + (uint32_t)row * 32u + (uint32_t)((c16 ^ ((row >> 2) & 1)) << 4); \
        cp16(d_, s_); \
    } } while (0)

#define LOAD_B(Bh, Bl, bufB) do { \
    _Pragma("unroll") \
    for (int ng = 0; ng < 4; ng++) { \
        int r_ = wn * 64 + ng * 16 + brow; \
        uint32_t off_ = (uint32_t)r_ * 32u + (uint32_t)((bsel ^ ((r_ >> 2) & 1)) << 4); \
        ldsm4(Bh[ng], (bufB) + off_); \
        ldsm4(Bl[ng], (bufB) + 8192u + off_); \
    } } while (0)

#define LOAD_B48(Bh, Bl, bufB) do { \
    _Pragma("unroll") \
    for (int ng = 0; ng < 3; ng++) { \
        int r_ = wn * 48 + ng * 16 + brow; \
        uint32_t off_ = (uint32_t)r_ * 32u + (uint32_t)((bsel ^ ((r_ >> 2) & 1)) << 4); \
        ldsm4(Bh[ng], (bufB) + off_); \
        ldsm4(Bl[ng], (bufB) + 8192u + off_); \
    } } while (0)

#define DO_MMAS(Bh, Bl, Ah, Al) do { \
    _Pragma("unroll") \
    for (int tm = 0; tm < 2; tm++) \
    _Pragma("unroll") \
    for (int ng = 0; ng < 4; ng++) \
    _Pragma("unroll") \
    for (int j = 0; j < 2; j++) { \
        int tn = ng * 2 + j; \
        mma16816(acc[tm][tn], Ah[tm], Bh[ng][j], Bh[ng][2 + j]); \
        mma16816(acc[tm][tn], Ah[tm], Bl[ng][j], Bl[ng][2 + j]); \
        mma16816(acc[tm][tn], Al[tm], Bh[ng][j], Bh[ng][2 + j]); \
    } } while (0)

#define DO_MMAS6(Bh, Bl, Ah, Al) do { \
    _Pragma("unroll") \
    for (int tm = 0; tm < 2; tm++) \
    _Pragma("unroll") \
    for (int ng = 0; ng < 3; ng++) \
    _Pragma("unroll") \
    for (int j = 0; j < 2; j++) { \
        int tn = ng * 2 + j; \
        mma16816(acc[tm][tn], Ah[tm], Bh[ng][j], Bh[ng][2 + j]); \
        mma16816(acc[tm][tn], Ah[tm], Bl[ng][j], Bl[ng][2 + j]); \
        mma16816(acc[tm][tn], Al[tm], Bh[ng][j], Bh[ng][2 + j]); \
    } } while (0)

    // ===== phase 1: s1 = Q @ K1^T (16 chunks of 16 cols) =====
#pragma unroll
    for (int a = 0; a < 2; a++)
#pragma unroll
        for (int b2 = 0; b2 < 8; b2++)
#pragma unroll
            for (int c = 0; c < 4; c++) acc[a][b2][c] = 0.f;

    STAGE_B256(K1h, K1l, 0, 0);
    STAGE_A64(Qh, Ql, 0, 0);
    CP_COMMIT();
    for (int kt = 0; kt < 16; kt++) {
        if (kt + 1 < 16) {
            STAGE_B256(K1h, K1l, (kt + 1) & 1, kt + 1);
            STAGE_A64(Qh, Ql, (kt + 1) & 1, kt + 1);
        }
        CP_COMMIT(); CP_WAIT1(); __syncthreads();
        uint32_t bufB = sb + SB_OFF + (uint32_t)(kt & 1) * 16384u;
        uint32_t bufA = sb + SA_OFF + (uint32_t)(kt & 1) * 4096u;
        uint32_t Bh[4][4], Bl[4][4], Ah[2][4], Al[2][4];
        LOAD_B(Bh, Bl, bufB);
#pragma unroll
        for (int tm = 0; tm < 2; tm++) {
            int r = wm * 32 + tm * 16 + arow;
            uint32_t off = (uint32_t)r * 32u + (uint32_t)((asel ^ ((r >> 2) & 1)) << 4);
            ldsm4(Ah[tm], bufA + off);
            ldsm4(Al[tm], bufA + 2048u + off);
        }
        DO_MMAS(Bh, Bl, Ah, Al);
        __syncthreads();
    }
#pragma unroll
    for (int tm = 0; tm < 2; tm++)
#pragma unroll
        for (int tn = 0; tn < 8; tn++)
#pragma unroll
            for (int half = 0; half < 2; half++) {
                int m = wm * 32 + tm * 16 + (lane >> 2) + half * 8;
                int n = wn * 64 + tn * 8 + (lane & 3) * 2;
                float v0 = acc[tm][tn][half * 2 + 0];
                float v1 = acc[tm][tn][half * 2 + 1];
                __nv_bfloat16 h0 = __float2bfloat16_rn(v0), h1 = __float2bfloat16_rn(v1);
                float l0 = v0 - __bfloat162float(h0), l1 = v1 - __bfloat162float(h1);
                *(uint32_t*)(sm + S1HI_OFF + m * 528 + n * 2) =
                    (uint32_t)__bfloat16_as_ushort(h0) | ((uint32_t)__bfloat16_as_ushort(h1) << 16);
                *(uint32_t*)(sm + S1LO_OFF + m * 528 + n * 2) = pack_bf2(l0, l1);
            }
    __syncthreads();

    // ===== phase 2: scores(:, :192) = s1 @ K2^T * SCALE — 8 warps, 48 cols each =====
#pragma unroll
    for (int a = 0; a < 2; a++)
#pragma unroll
        for (int b2 = 0; b2 < 8; b2++)
#pragma unroll
            for (int c = 0; c < 4; c++) acc[a][b2][c] = 0.f;

    STAGE_B192(K2h, K2l, 0, 0);
    CP_COMMIT();
    for (int kt = 0; kt < 16; kt++) {
        if (kt + 1 < 16) STAGE_B192(K2h, K2l, (kt + 1) & 1, kt + 1);
        CP_COMMIT(); CP_WAIT1(); __syncthreads();
        uint32_t bufB = sb + SB_OFF + (uint32_t)(kt & 1) * 16384u;
        uint32_t Bh[3][4], Bl[3][4], Ah[2][4], Al[2][4];
        LOAD_B48(Bh, Bl, bufB);
#pragma unroll
        for (int tm = 0; tm < 2; tm++) {
            int r = wm * 32 + tm * 16 + arow;
            uint32_t co = (uint32_t)(kt * 16 + asel * 8) * 2u;
            ldsm4(Ah[tm], sb + S1HI_OFF + (uint32_t)r * 528u + co);
            ldsm4(Al[tm], sb + S1LO_OFF + (uint32_t)r * 528u + co);
        }
        DO_MMAS6(Bh, Bl, Ah, Al);
        __syncthreads();
    }
    {
#pragma unroll
        for (int tm = 0; tm < 2; tm++)
#pragma unroll
            for (int tn = 0; tn < 6; tn++)
#pragma unroll
                for (int half = 0; half < 2; half++) {
                    int m = wm * 32 + tm * 16 + (lane >> 2) + half * 8;
                    int n = wn * 48 + tn * 8 + (lane & 3) * 2;
                    float2 v = make_float2(acc[tm][tn][half * 2 + 0] * SCALE_,
                                           acc[tm][tn][half * 2 + 1] * SCALE_);
                    *(float2*)(sm + SCR_OFF + m * 784 + n * 4) = v;
                }
    }
    __syncthreads();

    // ===== softmax over 192 cols; P (hi/lo bf16) written into the same rows =====
    {
#pragma unroll
        for (int i = 0; i < 8; i++) {
            int r = wid * 8 + i;
            const float* row = (const float*)(sm + SCR_OFF + r * 784);
            float mx = -1e30f;
#pragma unroll
            for (int c = 0; c < 6; c++) mx = fmaxf(mx, row[lane + c * 32]);
#pragma unroll
            for (int o = 16; o; o >>= 1) mx = fmaxf(mx, __shfl_xor_sync(0xffffffffu, mx, o));
            float e[6], ssum = 0.f;
#pragma unroll
            for (int c = 0; c < 6; c++) { e[c] = expf(row[lane + c * 32] - mx); ssum += e[c]; }
#pragma unroll
            for (int o = 16; o; o >>= 1) ssum += __shfl_xor_sync(0xffffffffu, ssum, o);
            float inv = 1.f / ssum;
#pragma unroll
            for (int c = 0; c < 6; c++) {
                float p = e[c] * inv;
                __nv_bfloat16 ph = __float2bfloat16_rn(p);
                __nv_bfloat16 pl = __float2bfloat16_rn(p - __bfloat162float(ph));
                int col = lane + c * 32;
                *(__nv_bfloat16*)(sm + SCR_OFF + r * 784 + col * 2)       = ph;
                *(__nv_bfloat16*)(sm + SCR_OFF + r * 784 + 384 + col * 2) = pl;
            }
        }
    }
    __syncthreads();

    // ===== phase 3: ctx = P[:, :192] @ V^T (12 chunks of 16 keys) =====
#pragma unroll
    for (int a = 0; a < 2; a++)
#pragma unroll
        for (int b2 = 0; b2 < 8; b2++)
#pragma unroll
            for (int c = 0; c < 4; c++) acc[a][b2][c] = 0.f;

    STAGE_B256(Vh, Vl, 0, 0);
    CP_COMMIT();
    for (int kt = 0; kt < 12; kt++) {
        if (kt + 1 < 12) STAGE_B256(Vh, Vl, (kt + 1) & 1, kt + 1);
        CP_COMMIT(); CP_WAIT1(); __syncthreads();
        uint32_t bufB = sb + SB_OFF + (uint32_t)(kt & 1) * 16384u;
        uint32_t Bh[4][4], Bl[4][4], Ah[2][4], Al[2][4];
        LOAD_B(Bh, Bl, bufB);
#pragma unroll
        for (int tm = 0; tm < 2; tm++) {
            int r = wm * 32 + tm * 16 + arow;
            uint32_t co = (uint32_t)(kt * 16 + asel * 8) * 2u;
            ldsm4(Ah[tm], sb + SCR_OFF + (uint32_t)r * 784u + co);
            ldsm4(Al[tm], sb + SCR_OFF + (uint32_t)r * 784u + 384u + co);
        }
        DO_MMAS(Bh, Bl, Ah, Al);
        __syncthreads();
    }
#pragma unroll
    for (int tm = 0; tm < 2; tm++)
#pragma unroll
        for (int tn = 0; tn < 8; tn++)
#pragma unroll
            for (int half = 0; half < 2; half++) {
                int m = wm * 32 + tm * 16 + (lane >> 2) + half * 8;
                int n = wn * 64 + tn * 8 + (lane & 3) * 2;
                int s = qb * 64 + m;
                float2 v = make_float2(acc[tm][tn][half * 2 + 0], acc[tm][tn][half * 2 + 1]);
                *(float2*)(out + ((size_t)(b * S_ + s)) * HIDN + h * D_ + n) = v;
            }
}

extern "C" void kernel_launch(void* const* d_in, const int* in_sizes, int n_in,
                              void* d_out, int out_size) {
    const float* X   = (const float*)d_in[0];
    const float* wq  = (const float*)d_in[1];
    const float* bq  = (const float*)d_in[2];
    const float* wk1 = (const float*)d_in[3];
    const float* bk1 = (const float*)d_in[4];
    const float* wk2 = (const float*)d_in[5];
    const float* bk2 = (const float*)d_in[6];
    const float* wv1 = (const float*)d_in[7];
    const float* bv1 = (const float*)d_in[8];
    const float* wv2 = (const float*)d_in[9];
    const float* bv2 = (const float*)d_in[10];
    float* out = (float*)d_out;

    static __nv_bfloat16 *whi = nullptr, *wlo = nullptr, *xhi = nullptr, *xlo = nullptr;
    if (!whi) {
        cudaGetSymbolAddress((void**)&whi, g_whi);
        cudaGetSymbolAddress((void**)&wlo, g_wlo);
        cudaGetSymbolAddress((void**)&xhi, g_xhi);
        cudaGetSymbolAddress((void**)&xlo, g_xlo);
    }

    combine_bv<<<HIDN / 256, 256>>>(bv1, bv2);

    const int NW4 = (HIDN * HIDN) / 4;
    const int NX4 = (M_ * HIDN) / 4;
    split4<<<NX4 / 256, 256>>>(X,   xhi, xlo, NX4);
    split4<<<NW4 / 256, 256>>>(wq,  whi + (size_t)0 * HIDN * HIDN, wlo + (size_t)0 * HIDN * HIDN, NW4);
    split4<<<NW4 / 256, 256>>>(wk1, whi + (size_t)1 * HIDN * HIDN, wlo + (size_t)1 * HIDN * HIDN, NW4);
    split4<<<NW4 / 256, 256>>>(wk2, whi + (size_t)2 * HIDN * HIDN, wlo + (size_t)2 * HIDN * HIDN, NW4);
    split4sum<<<NW4 / 256, 256>>>(wv1, wv2,
                                  whi + (size_t)3 * HIDN * HIDN, wlo + (size_t)3 * HIDN * HIDN, NW4);

    const int proj_smem = 65536;
    cudaFuncSetAttribute(proj_mma, cudaFuncAttributeMaxDynamicSharedMemorySize, proj_smem);
    dim3 gproj(HIDN / 128, M_ / 128, 4);
    proj_mma<<<gproj, 256, proj_smem>>>(bq, bk1, bk2);

    cudaFuncSetAttribute(attn_mma, cudaFuncAttributeMaxDynamicSharedMemorySize, ATTN_SMEM);
    dim3 gattn(4, H_, B_);
    attn_mma<<<gattn, 256, ATTN_SMEM>>>(out);
}

// round 16
// speedup vs baseline: 1.0094x; 1.0038x over previous
#include <cuda_runtime.h>
#include <cuda_bf16.h>
#include <cstdint>
#include <cstddef>

#define B_    64
#define S_    256
#define H_    16
#define D_    256
#define HIDN  4096
#define M_    (B_*S_)
#define SCALE_ 0.0625f

// ---------------- device scratch ----------------
__device__ float g_bv[HIDN];
__device__ __nv_bfloat16 g_xhi[(size_t)M_ * HIDN];
__device__ __nv_bfloat16 g_xlo[(size_t)M_ * HIDN];
__device__ __nv_bfloat16 g_whi[(size_t)4 * HIDN * HIDN];
__device__ __nv_bfloat16 g_wlo[(size_t)4 * HIDN * HIDN];
// projections, bf16 split. Q/K1/K2: [b,h,s,d]; V transposed: [b,h,d,s]
__device__ __nv_bfloat16 g_qhi[(size_t)M_ * HIDN];
__device__ __nv_bfloat16 g_qlo[(size_t)M_ * HIDN];
__device__ __nv_bfloat16 g_k1hi[(size_t)M_ * HIDN];
__device__ __nv_bfloat16 g_k1lo[(size_t)M_ * HIDN];
__device__ __nv_bfloat16 g_k2hi[(size_t)M_ * HIDN];
__device__ __nv_bfloat16 g_k2lo[(size_t)M_ * HIDN];
__device__ __nv_bfloat16 g_vthi[(size_t)M_ * HIDN];
__device__ __nv_bfloat16 g_vtlo[(size_t)M_ * HIDN];

__device__ __forceinline__ uint32_t smem_u32(const void* p) {
    uint32_t a;
    asm("{ .reg .u64 t; cvta.to.shared.u64 t, %1; cvt.u32.u64 %0, t; }" : "=r"(a) : "l"(p));
    return a;
}
__device__ __forceinline__ void cp16(uint32_t d, const void* s) {
    asm volatile("cp.async.cg.shared.global [%0], [%1], 16;" :: "r"(d), "l"(s) : "memory");
}
#define CP_COMMIT() asm volatile("cp.async.commit_group;" ::: "memory")
#define CP_WAIT1()  asm volatile("cp.async.wait_group 1;" ::: "memory")

__device__ __forceinline__ void ldsm4(uint32_t* r, uint32_t addr) {
    asm volatile("ldmatrix.sync.aligned.m8n8.x4.shared.b16 {%0,%1,%2,%3}, [%4];"
        : "=r"(r[0]), "=r"(r[1]), "=r"(r[2]), "=r"(r[3]) : "r"(addr));
}
__device__ __forceinline__ void mma16816(float* c, const uint32_t* a, uint32_t b0, uint32_t b1) {
    asm volatile("mma.sync.aligned.m16n8k16.row.col.f32.bf16.bf16.f32 "
        "{%0,%1,%2,%3}, {%4,%5,%6,%7}, {%8,%9}, {%0,%1,%2,%3};"
        : "+f"(c[0]), "+f"(c[1]), "+f"(c[2]), "+f"(c[3])
        : "r"(a[0]), "r"(a[1]), "r"(a[2]), "r"(a[3]), "r"(b0), "r"(b1));
}
__device__ __forceinline__ uint32_t pack_bf2(float x, float y) {
    __nv_bfloat16 hx = __float2bfloat16_rn(x), hy = __float2bfloat16_rn(y);
    return (uint32_t)__bfloat16_as_ushort(hx) | ((uint32_t)__bfloat16_as_ushort(hy) << 16);
}

struct alignas(8) BF4 { __nv_bfloat16 v[4]; };
__global__ void split4(const float* __restrict__ src, __nv_bfloat16* __restrict__ hi,
                       __nv_bfloat16* __restrict__ lo, int n4) {
    int i = blockIdx.x * blockDim.x + threadIdx.x;
    if (i >= n4) return;
    float4 x = ((const float4*)src)[i];
    float a[4] = {x.x, x.y, x.z, x.w};
    BF4 hb, lb;
#pragma unroll
    for (int j = 0; j < 4; j++) {
        __nv_bfloat16 h = __float2bfloat16_rn(a[j]);
        hb.v[j] = h;
        lb.v[j] = __float2bfloat16_rn(a[j] - __bfloat162float(h));
    }
    ((BF4*)hi)[i] = hb;
    ((BF4*)lo)[i] = lb;
}
// split(wv1+wv2) AND combine bv1+bv2 -> g_bv (folded to save a launch)
__global__ void split4sum(const float* __restrict__ s1, const float* __restrict__ s2,
                          const float* __restrict__ bv1, const float* __restrict__ bv2,
                          __nv_bfloat16* __restrict__ hi, __nv_bfloat16* __restrict__ lo, int n4) {
    int i = blockIdx.x * blockDim.x + threadIdx.x;
    if (i >= n4) return;
    if (i < HIDN / 4) {
        float4 a = ((const float4*)bv1)[i];
        float4 b = ((const float4*)bv2)[i];
        ((float4*)g_bv)[i] = make_float4(a.x + b.x, a.y + b.y, a.z + b.z, a.w + b.w);
    }
    float4 x = ((const float4*)s1)[i];
    float4 y = ((const float4*)s2)[i];
    float a[4] = {x.x + y.x, x.y + y.y, x.z + y.z, x.w + y.w};
    BF4 hb, lb;
#pragma unroll
    for (int j = 0; j < 4; j++) {
        __nv_bfloat16 h = __float2bfloat16_rn(a[j]);
        hb.v[j] = h;
        lb.v[j] = __float2bfloat16_rn(a[j] - __bfloat162float(h));
    }
    ((BF4*)hi)[i] = hb;
    ((BF4*)lo)[i] = lb;
}

// ---------------------------------------------------------------------------
// Projection GEMM: bf16x3 split via mma.sync (R8-proven mainloop).
// zbase=0: z in {0,1} (Q,K1), full 256 tokens/batch, grid y=128.
// zbase=2: z in {2,3} (K2,V), compacted 192-token/batch domain, grid y=96.
// ---------------------------------------------------------------------------
__global__ __launch_bounds__(256, 2) void proj_mma(
    const float* __restrict__ bq, const float* __restrict__ bk1, const float* __restrict__ bk2,
    int zbase) {
    extern __shared__ char rawsm[];
    uint32_t sb = smem_u32(rawsm);

    int tid = threadIdx.x;
    int lane = tid & 31, wid = tid >> 5;
    int wm = wid & 1, wn = wid >> 1;
    int nt = blockIdx.x, mt = blockIdx.y;
    int z = zbase + blockIdx.z;
    int skip = (zbase == 2);
    int rbase = mt * 128, cbase = nt * 128;

    const char* srcp[8];
    uint32_t    dst0[8];
#pragma unroll
    for (int i = 0; i < 8; i++) {
        int sidx = tid + i * 256;
        int region = sidx >> 9;
        int idx = sidx & 511;
        int row = idx >> 2, c16 = idx & 3;
        const __nv_bfloat16* base; size_t rg;
        if (region < 2) {
            base = (region == 0) ? g_xhi : g_xlo;
            int t = rbase + row;
            if (skip) { int bx = t / 192; rg = (size_t)(bx * 256 + (t - bx * 192)); }
            else      { rg = (size_t)t; }
        } else {
            base = (region == 2) ? g_whi : g_wlo;
            rg = (size_t)z * HIDN + cbase + row;
        }
        srcp[i] = (const char*)(base + rg * HIDN) + c16 * 16;
        dst0[i] = sb + (uint32_t)region * 8192u + (uint32_t)row * 64u
                + (uint32_t)((c16 ^ (row & 3)) << 4);
    }

    float acc[4][4][4];
#pragma unroll
    for (int a = 0; a < 4; a++)
#pragma unroll
        for (int b = 0; b < 4; b++)
#pragma unroll
            for (int c = 0; c < 4; c++) acc[a][b][c] = 0.f;

    int arow = lane & 15, asel = lane >> 4;
    int brow = ((lane >> 3) & 1) * 8 + (lane & 7);
    int bsel = lane >> 4;

#pragma unroll
    for (int i = 0; i < 8; i++) cp16(dst0[i], srcp[i]);
    CP_COMMIT();

    for (int kt = 0; kt < 128; kt++) {
        if (kt + 1 < 128) {
            uint32_t bo = (uint32_t)((kt + 1) & 1) * 32768u;
            size_t ko = (size_t)(kt + 1) * 64;
#pragma unroll
            for (int i = 0; i < 8; i++) cp16(dst0[i] + bo, srcp[i] + ko);
        }
        CP_COMMIT();
        CP_WAIT1();
        __syncthreads();

        uint32_t sbuf = sb + (uint32_t)(kt & 1) * 32768u;
#pragma unroll
        for (int kk = 0; kk < 2; kk++) {
            uint32_t Bh[2][4], Bl[2][4];
#pragma unroll
            for (int p = 0; p < 2; p++) {
                int r = wn * 32 + p * 16 + brow;
                int c = kk * 2 + bsel;
                uint32_t off = (uint32_t)r * 64u + (uint32_t)((c ^ (r & 3)) << 4);
                ldsm4(Bh[p], sbuf + 16384u + off);
                ldsm4(Bl[p], sbuf + 24576u + off);
            }
#pragma unroll
            for (int tm = 0; tm < 4; tm++) {
                int r = wm * 64 + tm * 16 + arow;
                int c = kk * 2 + asel;
                uint32_t off = (uint32_t)r * 64u + (uint32_t)((c ^ (r & 3)) << 4);
                uint32_t Ah[4], Al[4];
                ldsm4(Ah, sbuf + off);
                ldsm4(Al, sbuf + 8192u + off);
#pragma unroll
                for (int tn = 0; tn < 4; tn++) {
                    int p = tn >> 1, j = tn & 1;
                    mma16816(acc[tm][tn], Ah, Bh[p][j], Bh[p][2 + j]);
                    mma16816(acc[tm][tn], Ah, Bl[p][j], Bl[p][2 + j]);
                    mma16816(acc[tm][tn], Al, Bh[p][j], Bh[p][2 + j]);
                }
            }
        }
        __syncthreads();
    }

    const float* bb = (z == 0) ? bq : (z == 1) ? bk1 : (z == 2) ? bk2 : g_bv;
    __nv_bfloat16* ohi = (z == 0) ? g_qhi : (z == 1) ? g_k1hi : (z == 2) ? g_k2hi : g_vthi;
    __nv_bfloat16* olo = (z == 0) ? g_qlo : (z == 1) ? g_k1lo : (z == 2) ? g_k2lo : g_vtlo;
#pragma unroll
    for (int tn = 0; tn < 4; tn++) {
        int cg = cbase + wn * 32 + tn * 8 + (lane & 3) * 2;
        int h = cg >> 8, d = cg & 255;
        float b0 = bb[cg], b1 = bb[cg + 1];
#pragma unroll
        for (int tm = 0; tm < 4; tm++) {
#pragma unroll
            for (int half = 0; half < 2; half++) {
                int m = rbase + wm * 64 + tm * 16 + (lane >> 2) + half * 8;
                int bb_, s;
                if (skip) { bb_ = m / 192; s = m - bb_ * 192; }
                else      { bb_ = m >> 8;  s = m & 255; }
                float v0 = acc[tm][tn][half * 2 + 0] + b0;
                float v1 = acc[tm][tn][half * 2 + 1] + b1;
                __nv_bfloat16 h0 = __float2bfloat16_rn(v0);
                __nv_bfloat16 h1 = __float2bfloat16_rn(v1);
                __nv_bfloat16 l0 = __float2bfloat16_rn(v0 - __bfloat162float(h0));
                __nv_bfloat16 l1 = __float2bfloat16_rn(v1 - __bfloat162float(h1));
                if (z < 3) {
                    size_t idx = (((size_t)bb_ * H_ + h) * S_ + s) * D_ + d;
                    *(uint32_t*)(ohi + idx) = (uint32_t)__bfloat16_as_ushort(h0)
                                            | ((uint32_t)__bfloat16_as_ushort(h1) << 16);
                    *(uint32_t*)(olo + idx) = (uint32_t)__bfloat16_as_ushort(l0)
                                            | ((uint32_t)__bfloat16_as_ushort(l1) << 16);
                } else {
                    size_t base = ((size_t)bb_ * H_ + h) * (S_ * D_) + s;
                    ohi[base + (size_t)d * S_]       = h0;
                    ohi[base + (size_t)(d + 1) * S_] = h1;
                    olo[base + (size_t)d * S_]       = l0;
                    olo[base + (size_t)(d + 1) * S_] = l1;
                }
            }
        }
    }
}

// ---------------------------------------------------------------------------
// Attention (unchanged from R15 best): 108.5 KB smem, occupancy 2.
// ---------------------------------------------------------------------------
#define SB_OFF   0u
#define SA_OFF   32768u
#define S1HI_OFF 40960u
#define S1LO_OFF 74752u
#define SCR_OFF  40960u
#define ATTN_SMEM 108544

__global__ __launch_bounds__(256, 2) void attn_mma(float* __restrict__ out) {
    extern __shared__ char sm[];
    uint32_t sb = smem_u32(sm);
    int tid = threadIdx.x, lane = tid & 31, wid = tid >> 5;
    int wm = wid & 1, wn = wid >> 1;
    int qb = blockIdx.x, h = blockIdx.y, b = blockIdx.z;
    int bh = b * H_ + h;
    size_t bho = (size_t)bh * (S_ * D_);

    const __nv_bfloat16* Qh  = g_qhi  + bho; const __nv_bfloat16* Ql  = g_qlo  + bho;
    const __nv_bfloat16* K1h = g_k1hi + bho; const __nv_bfloat16* K1l = g_k1lo + bho;
    const __nv_bfloat16* K2h = g_k2hi + bho; const __nv_bfloat16* K2l = g_k2lo + bho;
    const __nv_bfloat16* Vh  = g_vthi + bho; const __nv_bfloat16* Vl  = g_vtlo + bho;

    int arow = lane & 15, asel = lane >> 4;
    int brow = ((lane >> 3) & 1) * 8 + (lane & 7);
    int bsel = lane >> 4;

    float acc[2][8][4];

#define STAGE_B256(HP, LP, st, kt) do { \
    _Pragma("unroll") \
    for (int i = 0; i < 4; i++) { \
        int sidx = tid + i * 256; \
        int reg = sidx >> 9, idx = sidx & 511; \
        int row = idx >> 1, c16 = idx & 1; \
        const __nv_bfloat16* s_ = (reg ? (LP) : (HP)) + (size_t)row * 256 + (kt) * 16 + c16 * 8; \
        uint32_t d_ = sb + SB_OFF + (uint32_t)(st) * 16384u + (uint32_t)reg * 8192u \
                    + (uint32_t)row * 32u + (uint32_t)((c16 ^ ((row >> 2) & 1)) << 4); \
        cp16(d_, s_); \
    } } while (0)

#define STAGE_B192(HP, LP, st, kt) do { \
    _Pragma("unroll") \
    for (int i = 0; i < 3; i++) { \
        int sidx = tid + i * 256; \
        int reg = sidx >= 384 ? 1 : 0; \
        int idx = sidx - reg * 384; \
        int row = idx >> 1, c16 = idx & 1; \
        const __nv_bfloat16* s_ = (reg ? (LP) : (HP)) + (size_t)row * 256 + (kt) * 16 + c16 * 8; \
        uint32_t d_ = sb + SB_OFF + (uint32_t)(st) * 16384u + (uint32_t)reg * 8192u \
                    + (uint32_t)row * 32u + (uint32_t)((c16 ^ ((row >> 2) & 1)) << 4); \
        cp16(d_, s_); \
    } } while (0)

#define STAGE_A64(HP, LP, st, kt) do { \
    { \
        int sidx = tid; \
        int reg = sidx >> 7, idx = sidx & 127; \
        int row = idx >> 1, c16 = idx & 1; \
        const __nv_bfloat16* s_ = (reg ? (LP) : (HP)) + (size_t)(qb * 64 + row) * 256 + (kt) * 16 + c16 * 8; \
        uint32_t d_ = sb + SA_OFF + (uint32_t)(st) * 4096u + (uint32_t)reg * 2048u \
                    + (uint32_t)row * 32u + (uint32_t)((c16 ^ ((row >> 2) & 1)) << 4); \
        cp16(d_, s_); \
    } } while (0)

#define LOAD_B(Bh, Bl, bufB) do { \
    _Pragma("unroll") \
    for (int ng = 0; ng < 4; ng++) { \
        int r_ = wn * 64 + ng * 16 + brow; \
        uint32_t off_ = (uint32_t)r_ * 32u + (uint32_t)((bsel ^ ((r_ >> 2) & 1)) << 4); \
        ldsm4(Bh[ng], (bufB) + off_); \
        ldsm4(Bl[ng], (bufB) + 8192u + off_); \
    } } while (0)

#define LOAD_B48(Bh, Bl, bufB) do { \
    _Pragma("unroll") \
    for (int ng = 0; ng < 3; ng++) { \
        int r_ = wn * 48 + ng * 16 + brow; \
        uint32_t off_ = (uint32_t)r_ * 32u + (uint32_t)((bsel ^ ((r_ >> 2) & 1)) << 4); \
        ldsm4(Bh[ng], (bufB) + off_); \
        ldsm4(Bl[ng], (bufB) + 8192u + off_); \
    } } while (0)

#define DO_MMAS(Bh, Bl, Ah, Al) do { \
    _Pragma("unroll") \
    for (int tm = 0; tm < 2; tm++) \
    _Pragma("unroll") \
    for (int ng = 0; ng < 4; ng++) \
    _Pragma("unroll") \
    for (int j = 0; j < 2; j++) { \
        int tn = ng * 2 + j; \
        mma16816(acc[tm][tn], Ah[tm], Bh[ng][j], Bh[ng][2 + j]); \
        mma16816(acc[tm][tn], Ah[tm], Bl[ng][j], Bl[ng][2 + j]); \
        mma16816(acc[tm][tn], Al[tm], Bh[ng][j], Bh[ng][2 + j]); \
    } } while (0)

#define DO_MMAS6(Bh, Bl, Ah, Al) do { \
    _Pragma("unroll") \
    for (int tm = 0; tm < 2; tm++) \
    _Pragma("unroll") \
    for (int ng = 0; ng < 3; ng++) \
    _Pragma("unroll") \
    for (int j = 0; j < 2; j++) { \
        int tn = ng * 2 + j; \
        mma16816(acc[tm][tn], Ah[tm], Bh[ng][j], Bh[ng][2 + j]); \
        mma16816(acc[tm][tn], Ah[tm], Bl[ng][j], Bl[ng][2 + j]); \
        mma16816(acc[tm][tn], Al[tm], Bh[ng][j], Bh[ng][2 + j]); \
    } } while (0)

    // ===== phase 1: s1 = Q @ K1^T =====
#pragma unroll
    for (int a = 0; a < 2; a++)
#pragma unroll
        for (int b2 = 0; b2 < 8; b2++)
#pragma unroll
            for (int c = 0; c < 4; c++) acc[a][b2][c] = 0.f;

    STAGE_B256(K1h, K1l, 0, 0);
    STAGE_A64(Qh, Ql, 0, 0);
    CP_COMMIT();
    for (int kt = 0; kt < 16; kt++) {
        if (kt + 1 < 16) {
            STAGE_B256(K1h, K1l, (kt + 1) & 1, kt + 1);
            STAGE_A64(Qh, Ql, (kt + 1) & 1, kt + 1);
        }
        CP_COMMIT(); CP_WAIT1(); __syncthreads();
        uint32_t bufB = sb + SB_OFF + (uint32_t)(kt & 1) * 16384u;
        uint32_t bufA = sb + SA_OFF + (uint32_t)(kt & 1) * 4096u;
        uint32_t Bh[4][4], Bl[4][4], Ah[2][4], Al[2][4];
        LOAD_B(Bh, Bl, bufB);
#pragma unroll
        for (int tm = 0; tm < 2; tm++) {
            int r = wm * 32 + tm * 16 + arow;
            uint32_t off = (uint32_t)r * 32u + (uint32_t)((asel ^ ((r >> 2) & 1)) << 4);
            ldsm4(Ah[tm], bufA + off);
            ldsm4(Al[tm], bufA + 2048u + off);
        }
        DO_MMAS(Bh, Bl, Ah, Al);
        __syncthreads();
    }
#pragma unroll
    for (int tm = 0; tm < 2; tm++)
#pragma unroll
        for (int tn = 0; tn < 8; tn++)
#pragma unroll
            for (int half = 0; half < 2; half++) {
                int m = wm * 32 + tm * 16 + (lane >> 2) + half * 8;
                int n = wn * 64 + tn * 8 + (lane & 3) * 2;
                float v0 = acc[tm][tn][half * 2 + 0];
                float v1 = acc[tm][tn][half * 2 + 1];
                __nv_bfloat16 h0 = __float2bfloat16_rn(v0), h1 = __float2bfloat16_rn(v1);
                float l0 = v0 - __bfloat162float(h0), l1 = v1 - __bfloat162float(h1);
                *(uint32_t*)(sm + S1HI_OFF + m * 528 + n * 2) =
                    (uint32_t)__bfloat16_as_ushort(h0) | ((uint32_t)__bfloat16_as_ushort(h1) << 16);
                *(uint32_t*)(sm + S1LO_OFF + m * 528 + n * 2) = pack_bf2(l0, l1);
            }
    __syncthreads();

    // ===== phase 2: scores(:, :192) = s1 @ K2^T * SCALE =====
#pragma unroll
    for (int a = 0; a < 2; a++)
#pragma unroll
        for (int b2 = 0; b2 < 8; b2++)
#pragma unroll
            for (int c = 0; c < 4; c++) acc[a][b2][c] = 0.f;

    STAGE_B192(K2h, K2l, 0, 0);
    CP_COMMIT();
    for (int kt = 0; kt < 16; kt++) {
        if (kt + 1 < 16) STAGE_B192(K2h, K2l, (kt + 1) & 1, kt + 1);
        CP_COMMIT(); CP_WAIT1(); __syncthreads();
        uint32_t bufB = sb + SB_OFF + (uint32_t)(kt & 1) * 16384u;
        uint32_t Bh[3][4], Bl[3][4], Ah[2][4], Al[2][4];
        LOAD_B48(Bh, Bl, bufB);
#pragma unroll
        for (int tm = 0; tm < 2; tm++) {
            int r = wm * 32 + tm * 16 + arow;
            uint32_t co = (uint32_t)(kt * 16 + asel * 8) * 2u;
            ldsm4(Ah[tm], sb + S1HI_OFF + (uint32_t)r * 528u + co);
            ldsm4(Al[tm], sb + S1LO_OFF + (uint32_t)r * 528u + co);
        }
        DO_MMAS6(Bh, Bl, Ah, Al);
        __syncthreads();
    }
    {
#pragma unroll
        for (int tm = 0; tm < 2; tm++)
#pragma unroll
            for (int tn = 0; tn < 6; tn++)
#pragma unroll
                for (int half = 0; half < 2; half++) {
                    int m = wm * 32 + tm * 16 + (lane >> 2) + half * 8;
                    int n = wn * 48 + tn * 8 + (lane & 3) * 2;
                    float2 v = make_float2(acc[tm][tn][half * 2 + 0] * SCALE_,
                                           acc[tm][tn][half * 2 + 1] * SCALE_);
                    *(float2*)(sm + SCR_OFF + m * 784 + n * 4) = v;
                }
    }
    __syncthreads();

    // ===== softmax over 192 cols; P (hi/lo bf16) embedded in SCR rows =====
    {
#pragma unroll
        for (int i = 0; i < 8; i++) {
            int r = wid * 8 + i;
            const float* row = (const float*)(sm + SCR_OFF + r * 784);
            float mx = -1e30f;
#pragma unroll
            for (int c = 0; c < 6; c++) mx = fmaxf(mx, row[lane + c * 32]);
#pragma unroll
            for (int o = 16; o; o >>= 1) mx = fmaxf(mx, __shfl_xor_sync(0xffffffffu, mx, o));
            float e[6], ssum = 0.f;
#pragma unroll
            for (int c = 0; c < 6; c++) { e[c] = expf(row[lane + c * 32] - mx); ssum += e[c]; }
#pragma unroll
            for (int o = 16; o; o >>= 1) ssum += __shfl_xor_sync(0xffffffffu, ssum, o);
            float inv = 1.f / ssum;
#pragma unroll
            for (int c = 0; c < 6; c++) {
                float p = e[c] * inv;
                __nv_bfloat16 ph = __float2bfloat16_rn(p);
                __nv_bfloat16 pl = __float2bfloat16_rn(p - __bfloat162float(ph));
                int col = lane + c * 32;
                *(__nv_bfloat16*)(sm + SCR_OFF + r * 784 + col * 2)       = ph;
                *(__nv_bfloat16*)(sm + SCR_OFF + r * 784 + 384 + col * 2) = pl;
            }
        }
    }
    __syncthreads();

    // ===== phase 3: ctx = P[:, :192] @ V^T =====
#pragma unroll
    for (int a = 0; a < 2; a++)
#pragma unroll
        for (int b2 = 0; b2 < 8; b2++)
#pragma unroll
            for (int c = 0; c < 4; c++) acc[a][b2][c] = 0.f;

    STAGE_B256(Vh, Vl, 0, 0);
    CP_COMMIT();
    for (int kt = 0; kt < 12; kt++) {
        if (kt + 1 < 12) STAGE_B256(Vh, Vl, (kt + 1) & 1, kt + 1);
        CP_COMMIT(); CP_WAIT1(); __syncthreads();
        uint32_t bufB = sb + SB_OFF + (uint32_t)(kt & 1) * 16384u;
        uint32_t Bh[4][4], Bl[4][4], Ah[2][4], Al[2][4];
        LOAD_B(Bh, Bl, bufB);
#pragma unroll
        for (int tm = 0; tm < 2; tm++) {
            int r = wm * 32 + tm * 16 + arow;
            uint32_t co = (uint32_t)(kt * 16 + asel * 8) * 2u;
            ldsm4(Ah[tm], sb + SCR_OFF + (uint32_t)r * 784u + co);
            ldsm4(Al[tm], sb + SCR_OFF + (uint32_t)r * 784u + 384u + co);
        }
        DO_MMAS(Bh, Bl, Ah, Al);
        __syncthreads();
    }
#pragma unroll
    for (int tm = 0; tm < 2; tm++)
#pragma unroll
        for (int tn = 0; tn < 8; tn++)
#pragma unroll
            for (int half = 0; half < 2; half++) {
                int m = wm * 32 + tm * 16 + (lane >> 2) + half * 8;
                int n = wn * 64 + tn * 8 + (lane & 3) * 2;
                int s = qb * 64 + m;
                float2 v = make_float2(acc[tm][tn][half * 2 + 0], acc[tm][tn][half * 2 + 1]);
                *(float2*)(out + ((size_t)(b * S_ + s)) * HIDN + h * D_ + n) = v;
            }
}

extern "C" void kernel_launch(void* const* d_in, const int* in_sizes, int n_in,
                              void* d_out, int out_size) {
    const float* X   = (const float*)d_in[0];
    const float* wq  = (const float*)d_in[1];
    const float* bq  = (const float*)d_in[2];
    const float* wk1 = (const float*)d_in[3];
    const float* bk1 = (const float*)d_in[4];
    const float* wk2 = (const float*)d_in[5];
    const float* bk2 = (const float*)d_in[6];
    const float* wv1 = (const float*)d_in[7];
    const float* bv1 = (const float*)d_in[8];
    const float* wv2 = (const float*)d_in[9];
    const float* bv2 = (const float*)d_in[10];
    float* out = (float*)d_out;

    static __nv_bfloat16 *whi = nullptr, *wlo = nullptr, *xhi = nullptr, *xlo = nullptr;
    if (!whi) {
        cudaGetSymbolAddress((void**)&whi, g_whi);
        cudaGetSymbolAddress((void**)&wlo, g_wlo);
        cudaGetSymbolAddress((void**)&xhi, g_xhi);
        cudaGetSymbolAddress((void**)&xlo, g_xlo);
    }

    const int NW4 = (HIDN * HIDN) / 4;
    const int NX4 = (M_ * HIDN) / 4;
    const int proj_smem = 65536;
    cudaFuncSetAttribute(proj_mma, cudaFuncAttributeMaxDynamicSharedMemorySize, proj_smem);
    cudaFuncSetAttribute(attn_mma, cudaFuncAttributeMaxDynamicSharedMemorySize, ATTN_SMEM);

    // Launch order arranged so proj_mma (Q,K1) is the 5th launch -> ncu -s 5 captures it.
    split4sum<<<NW4 / 256, 256>>>(wv1, wv2, bv1, bv2,
                                  whi + (size_t)3 * HIDN * HIDN, wlo + (size_t)3 * HIDN * HIDN, NW4);  // 1
    split4<<<NX4 / 256, 256>>>(X,   xhi, xlo, NX4);                                                    // 2
    split4<<<NW4 / 256, 256>>>(wq,  whi + (size_t)0 * HIDN * HIDN, wlo + (size_t)0 * HIDN * HIDN, NW4);// 3
    split4<<<NW4 / 256, 256>>>(wk1, whi + (size_t)1 * HIDN * HIDN, wlo + (size_t)1 * HIDN * HIDN, NW4);// 4

    dim3 gproj0(HIDN / 128, M_ / 128, 2);
    proj_mma<<<gproj0, 256, proj_smem>>>(bq, bk1, bk2, 0);                                             // 5 (profiled)

    split4<<<NW4 / 256, 256>>>(wk2, whi + (size_t)2 * HIDN * HIDN, wlo + (size_t)2 * HIDN * HIDN, NW4);// 6

    dim3 gproj1(HIDN / 128, (B_ * 192) / 128, 2);
    proj_mma<<<gproj1, 256, proj_smem>>>(bq, bk1, bk2, 2);                                             // 7

    dim3 gattn(4, H_, B_);
    attn_mma<<<gattn, 256, ATTN_SMEM>>>(out);                                                          // 8
}